// round 2
// baseline (speedup 1.0000x reference)
#include <cuda_runtime.h>
#include <math.h>

// ---------------------------------------------------------------------------
// Problem constants
//   B=4, S=1024, H=1024, HEADS=16, HEAD_D=64, MEM_LEN=1024, K=2048
// ---------------------------------------------------------------------------
#define PLANE 2097152ull   // 1024*2048 (one (b,n) score plane)

// Device-global scratch (no cudaMalloc allowed)
__device__ float g_KV [(size_t)8192 * 1024];                // kv_in natural flat order, row = b*2048+j
__device__ float g_Q  [(size_t)4096 * 1024];                // q proj, flat row order of TE
__device__ float g_K  [(size_t)8192 * 1024];                // k proj, flat row order of kv_in
__device__ float g_V  [(size_t)8192 * 1024];                // v proj, flat row order of kv_in
__device__ float g_R  [(size_t)2048 * 1024];                // kr proj, row = l
__device__ float g_AC [(size_t)64 * PLANE];                 // [b*16+n][i][j]
__device__ float g_BD [(size_t)64 * PLANE];                 // [b*16+n][i][l] (unshifted)
__device__ float g_ATT[(size_t)64 * PLANE];                 // [b*16+n][i][j]
__device__ float g_O1 [(size_t)4096 * 1024];                // pre-O-proj out, flat row = i*4+b

// ---------------------------------------------------------------------------
// Gather kv_in in NATURAL flat order: row r = b*2048 + j
//   (j<1024 ? TE[b,j] : mems[0,b,j-1024])
// The (K,B,heads,d) reshape downstream is a flat reinterpretation, so
// k[j,b] = proj flat row (j*4+b) — consumers index that way directly.
// ---------------------------------------------------------------------------
__global__ void gather_kv(const float4* __restrict__ te, const float4* __restrict__ mems)
{
    int idx = blockIdx.x * blockDim.x + threadIdx.x;        // over 8192*256 float4
    int row = idx >> 8;                                     // 0..8191  (b*2048 + j)
    int c   = idx & 255;
    int b = row >> 11, j = row & 2047;
    float4 v;
    if (j < 1024) v = te  [((size_t)b * 1024 + j) * 256 + c];
    else          v = mems[((size_t)b * 2048 + (j - 1024)) * 256 + c];
    ((float4*)g_KV)[idx] = v;
}

// ---------------------------------------------------------------------------
// SGEMM NT: C[M,N] = A[M,K] @ W[N,K]^T + bias[N]
// 128x128 block tile, BK=16, 256 threads, split 8x8 micro-tile (4+4 rows/cols)
// ---------------------------------------------------------------------------
__global__ void __launch_bounds__(256) sgemm_nt(
    const float* __restrict__ A, const float* __restrict__ W,
    const float* __restrict__ bias, float* __restrict__ C,
    int M, int N, int K)
{
    __shared__ float As[16][128];
    __shared__ float Bs[16][128];
    const int tid = threadIdx.x;
    const int m0 = blockIdx.y * 128;
    const int n0 = blockIdx.x * 128;
    const int lr = tid >> 2;                 // 0..63
    const int lc = (tid & 3) << 2;           // 0,4,8,12
    const float* Ap = A + (size_t)(m0 + lr) * K + lc;
    const float* Wp = W + (size_t)(n0 + lr) * K + lc;
    const int ty = tid >> 4, tx = tid & 15;

    float acc[8][8];
#pragma unroll
    for (int i = 0; i < 8; i++)
#pragma unroll
        for (int j = 0; j < 8; j++) acc[i][j] = 0.f;

    for (int k0 = 0; k0 < K; k0 += 16) {
        float4 a0 = *(const float4*)(Ap);
        float4 a1 = *(const float4*)(Ap + (size_t)64 * K);
        float4 w0 = *(const float4*)(Wp);
        float4 w1 = *(const float4*)(Wp + (size_t)64 * K);
        __syncthreads();
        As[lc+0][lr] = a0.x; As[lc+1][lr] = a0.y; As[lc+2][lr] = a0.z; As[lc+3][lr] = a0.w;
        As[lc+0][lr+64] = a1.x; As[lc+1][lr+64] = a1.y; As[lc+2][lr+64] = a1.z; As[lc+3][lr+64] = a1.w;
        Bs[lc+0][lr] = w0.x; Bs[lc+1][lr] = w0.y; Bs[lc+2][lr] = w0.z; Bs[lc+3][lr] = w0.w;
        Bs[lc+0][lr+64] = w1.x; Bs[lc+1][lr+64] = w1.y; Bs[lc+2][lr+64] = w1.z; Bs[lc+3][lr+64] = w1.w;
        __syncthreads();
#pragma unroll
        for (int k = 0; k < 16; k++) {
            float a[8], b[8];
            *(float4*)(&a[0]) = *(const float4*)(&As[k][ty*4]);
            *(float4*)(&a[4]) = *(const float4*)(&As[k][64 + ty*4]);
            *(float4*)(&b[0]) = *(const float4*)(&Bs[k][tx*4]);
            *(float4*)(&b[4]) = *(const float4*)(&Bs[k][64 + tx*4]);
#pragma unroll
            for (int im = 0; im < 8; im++)
#pragma unroll
                for (int in = 0; in < 8; in++)
                    acc[im][in] += a[im] * b[in];
        }
        Ap += 16; Wp += 16;
    }

#pragma unroll
    for (int h = 0; h < 2; h++)
#pragma unroll
        for (int r = 0; r < 4; r++) {
            int row = m0 + h*64 + ty*4 + r;
            float* cp = C + (size_t)row * N + n0;
#pragma unroll
            for (int g = 0; g < 2; g++) {
                int col = g*64 + tx*4;
                float4 bb = *(const float4*)(bias + n0 + col);
                float4 o;
                o.x = acc[h*4+r][g*4+0] + bb.x;
                o.y = acc[h*4+r][g*4+1] + bb.y;
                o.z = acc[h*4+r][g*4+2] + bb.z;
                o.w = acc[h*4+r][g*4+3] + bb.w;
                *(float4*)(cp + col) = o;
            }
        }
}

// ---------------------------------------------------------------------------
// Batched scores GEMM over z = b*16+n.
//   mode 0 (AC):  C[i,j] = sum_d (q[i,b,n,d]+u[n,d]) * k[j,b,n,d]   -> g_AC
//   mode 1 (BD):  C[i,l] = sum_d (q[i,b,n,d]+v[n,d]) * kr[l,n,d]    -> g_BD
// q[i,b] = g_Q flat row (i*4+b); k[j,b] = g_K flat row (j*4+b).
// 128(i) x 128(j) tiles, K-dim 64, BK=16.
// ---------------------------------------------------------------------------
__global__ void __launch_bounds__(256) scores_nt(const float* __restrict__ addv, int mode)
{
    const int z = blockIdx.z;
    const int b = z >> 4, n = z & 15;
    const float* Bm  = mode ? g_R  : g_K;
    float*       Out = mode ? g_BD : g_AC;
    const size_t ldb  = mode ? 1024 : 4096;
    const size_t boff = mode ? 0 : (size_t)b * 1024;

    __shared__ float As[16][128];
    __shared__ float Bs[16][128];
    const int tid = threadIdx.x;
    const int i0 = blockIdx.y * 128;
    const int j0 = blockIdx.x * 128;
    const int lr = tid >> 2;
    const int lc = (tid & 3) << 2;
    const float* Ap = g_Q + ((size_t)(i0 + lr) * 4 + b) * 1024 + n*64 + lc;
    const float* Bp = Bm + (size_t)(j0 + lr) * ldb + boff + n*64 + lc;
    const float* up = addv + n*64 + lc;
    const int ty = tid >> 4, tx = tid & 15;

    float acc[8][8];
#pragma unroll
    for (int i = 0; i < 8; i++)
#pragma unroll
        for (int j = 0; j < 8; j++) acc[i][j] = 0.f;

#pragma unroll
    for (int k0 = 0; k0 < 64; k0 += 16) {
        float4 uv = *(const float4*)(up);
        float4 a0 = *(const float4*)(Ap);
        float4 a1 = *(const float4*)(Ap + (size_t)64 * 4 * 1024);
        a0.x += uv.x; a0.y += uv.y; a0.z += uv.z; a0.w += uv.w;
        a1.x += uv.x; a1.y += uv.y; a1.z += uv.z; a1.w += uv.w;
        float4 w0 = *(const float4*)(Bp);
        float4 w1 = *(const float4*)(Bp + (size_t)64 * ldb);
        __syncthreads();
        As[lc+0][lr] = a0.x; As[lc+1][lr] = a0.y; As[lc+2][lr] = a0.z; As[lc+3][lr] = a0.w;
        As[lc+0][lr+64] = a1.x; As[lc+1][lr+64] = a1.y; As[lc+2][lr+64] = a1.z; As[lc+3][lr+64] = a1.w;
        Bs[lc+0][lr] = w0.x; Bs[lc+1][lr] = w0.y; Bs[lc+2][lr] = w0.z; Bs[lc+3][lr] = w0.w;
        Bs[lc+0][lr+64] = w1.x; Bs[lc+1][lr+64] = w1.y; Bs[lc+2][lr+64] = w1.z; Bs[lc+3][lr+64] = w1.w;
        __syncthreads();
#pragma unroll
        for (int k = 0; k < 16; k++) {
            float a[8], bb[8];
            *(float4*)(&a[0])  = *(const float4*)(&As[k][ty*4]);
            *(float4*)(&a[4])  = *(const float4*)(&As[k][64 + ty*4]);
            *(float4*)(&bb[0]) = *(const float4*)(&Bs[k][tx*4]);
            *(float4*)(&bb[4]) = *(const float4*)(&Bs[k][64 + tx*4]);
#pragma unroll
            for (int im = 0; im < 8; im++)
#pragma unroll
                for (int in = 0; in < 8; in++)
                    acc[im][in] += a[im] * bb[in];
        }
        Ap += 16; Bp += 16; up += 16;
    }

    const size_t obase = (size_t)z * PLANE;
#pragma unroll
    for (int h = 0; h < 2; h++)
#pragma unroll
        for (int r = 0; r < 4; r++) {
            int row = i0 + h*64 + ty*4 + r;
            float* cp = Out + obase + (size_t)row * 2048 + j0;
#pragma unroll
            for (int g = 0; g < 2; g++) {
                int col = g*64 + tx*4;
                float4 o;
                o.x = acc[h*4+r][g*4+0];
                o.y = acc[h*4+r][g*4+1];
                o.z = acc[h*4+r][g*4+2];
                o.w = acc[h*4+r][g*4+3];
                *(float4*)(cp + col) = o;
            }
        }
}

// ---------------------------------------------------------------------------
// Softmax over the 16-head axis (faithful to reference), with rel-shift of BD
// and the (no-op for all-ones mask) faithful mask remap.
//   s[n] = (AC[b,n,i,j] + (l<2048 ? BD[b,n,i,l] : 0)) / 8 - big
//   l = j + 1023 - i ;  big uses b'=i>>8, j'=(64j+16b+n)&2047
// ---------------------------------------------------------------------------
__global__ void softmax_heads(const float* __restrict__ amask)
{
    const int j = blockIdx.x * 256 + threadIdx.x;   // 0..2047
    const int i = blockIdx.y;                        // 0..1023
    const int b = blockIdx.z;                        // 0..3
    const int l = j + 1023 - i;
    const bool lv = (l < 2048);
    const int bprime = i >> 8;

    const size_t base = ((size_t)b * 16 * 1024 + i) * 2048;
    float s[16];
    float mx = -1e30f;
#pragma unroll
    for (int n = 0; n < 16; n++) {
        float ac = g_AC[base + (size_t)n * PLANE + j];
        float bd = lv ? g_BD[base + (size_t)n * PLANE + l] : 0.f;
        float val = (ac + bd) * 0.125f;
        int jp = (j * 64 + b * 16 + n) & 2047;
        float m = (jp < 1024) ? 1.f : amask[(size_t)bprime * 1024 + (jp - 1024)];
        val -= (1.f - m) * 1e9f;
        s[n] = val;
        mx = fmaxf(mx, val);
    }
    float sum = 0.f;
#pragma unroll
    for (int n = 0; n < 16; n++) { s[n] = __expf(s[n] - mx); sum += s[n]; }
    float inv = 1.f / sum;
#pragma unroll
    for (int n = 0; n < 16; n++)
        g_ATT[base + (size_t)n * PLANE + j] = s[n] * inv;
}

// ---------------------------------------------------------------------------
// attn @ V, batched over z=b*16+n:  O1 flat row (i*4+b), col n*64+d
//   = sum_j ATT[z,i,j] * v[j,b,n,d]  ;  v[j,b] = g_V flat row (j*4+b)
// 128(i) x 64(d) tile, BK=32, 256 threads, 8x4 micro.
// ---------------------------------------------------------------------------
__global__ void __launch_bounds__(256) attnv_nt()
{
    const int z = blockIdx.y;
    const int b = z >> 4, n = z & 15;
    __shared__ float As[32][128];
    __shared__ float Bs[32][64];
    const int tid = threadIdx.x;
    const int i0 = blockIdx.x * 128;
    const size_t zbase = (size_t)z * PLANE;

    const int alr = tid >> 1, alc = (tid & 1) << 4;   // A: 128 rows x 32 cols
    const int blr = tid >> 3, blc = (tid & 7) << 3;   // B: 32 rows x 64 cols
    const float* Ap = g_ATT + zbase + (size_t)(i0 + alr) * 2048 + alc;
    const float* Bp = g_V + ((size_t)blr * 4 + b) * 1024 + n*64 + blc;
    const int ty = tid >> 4, tx = tid & 15;

    float acc[8][4];
#pragma unroll
    for (int i = 0; i < 8; i++)
#pragma unroll
        for (int j = 0; j < 4; j++) acc[i][j] = 0.f;

    for (int k0 = 0; k0 < 2048; k0 += 32) {
        float4 a0 = *(const float4*)(Ap);
        float4 a1 = *(const float4*)(Ap + 4);
        float4 a2 = *(const float4*)(Ap + 8);
        float4 a3 = *(const float4*)(Ap + 12);
        float4 v0 = *(const float4*)(Bp);
        float4 v1 = *(const float4*)(Bp + 4);
        __syncthreads();
        As[alc+ 0][alr] = a0.x; As[alc+ 1][alr] = a0.y; As[alc+ 2][alr] = a0.z; As[alc+ 3][alr] = a0.w;
        As[alc+ 4][alr] = a1.x; As[alc+ 5][alr] = a1.y; As[alc+ 6][alr] = a1.z; As[alc+ 7][alr] = a1.w;
        As[alc+ 8][alr] = a2.x; As[alc+ 9][alr] = a2.y; As[alc+10][alr] = a2.z; As[alc+11][alr] = a2.w;
        As[alc+12][alr] = a3.x; As[alc+13][alr] = a3.y; As[alc+14][alr] = a3.z; As[alc+15][alr] = a3.w;
        *(float4*)(&Bs[blr][blc])     = v0;
        *(float4*)(&Bs[blr][blc + 4]) = v1;
        __syncthreads();
#pragma unroll
        for (int k = 0; k < 32; k++) {
            float a[8], bb[4];
            *(float4*)(&a[0])  = *(const float4*)(&As[k][ty*4]);
            *(float4*)(&a[4])  = *(const float4*)(&As[k][64 + ty*4]);
            *(float4*)(&bb[0]) = *(const float4*)(&Bs[k][tx*4]);
#pragma unroll
            for (int im = 0; im < 8; im++)
#pragma unroll
                for (int in = 0; in < 4; in++)
                    acc[im][in] += a[im] * bb[in];
        }
        Ap += 32;
        Bp += (size_t)32 * 4 * 1024;
    }

#pragma unroll
    for (int h = 0; h < 2; h++)
#pragma unroll
        for (int r = 0; r < 4; r++) {
            int i = i0 + h*64 + ty*4 + r;
            float* op = g_O1 + ((size_t)i * 4 + b) * 1024 + n*64 + tx*4;
            float4 o;
            o.x = acc[h*4+r][0]; o.y = acc[h*4+r][1];
            o.z = acc[h*4+r][2]; o.w = acc[h*4+r][3];
            *(float4*)op = o;
        }
}

// ---------------------------------------------------------------------------
// mems_new: copy mems, overwriting [0, b, 1024:2048, :] with out[b, s, :]
// ---------------------------------------------------------------------------
__global__ void write_mems(const float4* __restrict__ mems,
                           const float4* __restrict__ out,
                           float4* __restrict__ dst)
{
    int idx = blockIdx.x * blockDim.x + threadIdx.x;  // over 4*2048*256 float4
    int row = idx >> 8;        // b*2048 + pos
    int c   = idx & 255;
    int b   = row >> 11;
    int pos = row & 2047;
    float4 v;
    if (pos < 1024) v = mems[idx];
    else            v = out[(((size_t)b * 1024) + (pos - 1024)) * 256 + c];
    dst[idx] = v;
}

// ---------------------------------------------------------------------------
extern "C" void kernel_launch(void* const* d_in, const int* in_sizes, int n_in,
                              void* d_out, int out_size)
{
    const float* TE    = (const float*)d_in[0];
    const float* REL   = (const float*)d_in[1];
    const float* MEMS  = (const float*)d_in[2];
    const float* AMASK = (const float*)d_in[3];
    const float* Wq = (const float*)d_in[4],  *bq = (const float*)d_in[5];
    const float* Wk = (const float*)d_in[6],  *bk = (const float*)d_in[7];
    const float* Wv = (const float*)d_in[8],  *bv = (const float*)d_in[9];
    const float* Wr = (const float*)d_in[10], *br = (const float*)d_in[11];
    const float* Wo = (const float*)d_in[12], *bo = (const float*)d_in[13];
    const float* u  = (const float*)d_in[14];
    const float* v  = (const float*)d_in[15];
    float* out = (float*)d_out;

    float *pKV, *pQ, *pK, *pV, *pR, *pO1;
    cudaGetSymbolAddress((void**)&pKV, g_KV);
    cudaGetSymbolAddress((void**)&pQ,  g_Q);
    cudaGetSymbolAddress((void**)&pK,  g_K);
    cudaGetSymbolAddress((void**)&pV,  g_V);
    cudaGetSymbolAddress((void**)&pR,  g_R);
    cudaGetSymbolAddress((void**)&pO1, g_O1);

    // 1. gather kv rows in natural flat order (row = b*2048+j)
    gather_kv<<<8192, 256>>>((const float4*)TE, (const float4*)MEMS);
    // 2. projections (NT GEMMs + bias)
    sgemm_nt<<<dim3(8, 32), 256>>>(TE,  Wq, bq, pQ, 4096, 1024, 1024);
    sgemm_nt<<<dim3(8, 64), 256>>>(pKV, Wk, bk, pK, 8192, 1024, 1024);
    sgemm_nt<<<dim3(8, 64), 256>>>(pKV, Wv, bv, pV, 8192, 1024, 1024);
    sgemm_nt<<<dim3(8, 16), 256>>>(REL, Wr, br, pR, 2048, 1024, 1024);
    // 3. score GEMMs: AC (q+u vs K) and unshifted BD (q+v vs R)
    scores_nt<<<dim3(16, 8, 64), 256>>>(u, 0);
    scores_nt<<<dim3(16, 8, 64), 256>>>(v, 1);
    // 4. rel-shift + mask + softmax over heads
    softmax_heads<<<dim3(8, 1024, 4), 256>>>(AMASK);
    // 5. attn @ V
    attnv_nt<<<dim3(8, 64), 256>>>();
    // 6. output projection straight into d_out
    sgemm_nt<<<dim3(8, 32), 256>>>(pO1, Wo, bo, out, 4096, 1024, 1024);
    // 7. mems_new (second tuple output), if the buffer carries it
    if (out_size >= 12582912)
        write_mems<<<8192, 256>>>((const float4*)MEMS, (const float4*)out,
                                  (float4*)(out + 4194304));
}

// round 4
// speedup vs baseline: 1.9612x; 1.9612x over previous
#include <cuda_runtime.h>
#include <cuda_bf16.h>
#include <stdint.h>
#include <math.h>

// ---------------------------------------------------------------------------
// Problem constants: B=4, S=1024, H=1024, HEADS=16, HEAD_D=64, K=2048
// ---------------------------------------------------------------------------
#define PLANE 2097152ull   // 1024*2048

// ---------------- fp32 scratch ----------------
__device__ float g_KV [(size_t)8192 * 1024];
__device__ float g_Q  [(size_t)4096 * 1024];
__device__ float g_K  [(size_t)8192 * 1024];
__device__ float g_V  [(size_t)8192 * 1024];
__device__ float g_R  [(size_t)2048 * 1024];
__device__ float g_AC [(size_t)64 * PLANE];
__device__ float g_BD [(size_t)64 * PLANE];
__device__ float g_O1 [(size_t)4096 * 1024];

// ---------------- bf16 split scratch ----------------
__device__ __nv_bfloat16 g_TEh [(size_t)4096*1024], g_TEl [(size_t)4096*1024];
__device__ __nv_bfloat16 g_KVh [(size_t)8192*1024], g_KVl [(size_t)8192*1024];
__device__ __nv_bfloat16 g_RELh[(size_t)2048*1024], g_RELl[(size_t)2048*1024];
__device__ __nv_bfloat16 g_O1h [(size_t)4096*1024], g_O1l [(size_t)4096*1024];
__device__ __nv_bfloat16 g_Wh  [(size_t)5*1024*1024], g_Wl [(size_t)5*1024*1024];
__device__ __nv_bfloat16 g_QUh [(size_t)4096*1024], g_QUl [(size_t)4096*1024];
__device__ __nv_bfloat16 g_QVh [(size_t)4096*1024], g_QVl [(size_t)4096*1024];
__device__ __nv_bfloat16 g_Kh  [(size_t)8192*1024], g_Kl  [(size_t)8192*1024];
__device__ __nv_bfloat16 g_Rh  [(size_t)2048*1024], g_Rl  [(size_t)2048*1024];
__device__ __nv_bfloat16 g_Vh  [(size_t)8192*1024], g_Vl  [(size_t)8192*1024];
__device__ __nv_bfloat16 g_ATTh[(size_t)64 * PLANE], g_ATTl[(size_t)64 * PLANE];

// ---------------------------------------------------------------------------
// Low-level helpers (sm_80-compatible ISA only: ldmatrix / mma.sync / cp.async)
// ---------------------------------------------------------------------------
__device__ __forceinline__ uint32_t smem_u32(const void* p) {
    uint32_t a;
    asm("{ .reg .u64 t; cvta.to.shared.u64 t, %1; cvt.u32.u64 %0, t; }"
        : "=r"(a) : "l"(p));
    return a;
}

__device__ __forceinline__ void ldsm4(uint32_t* r, uint32_t a) {
    asm volatile("ldmatrix.sync.aligned.m8n8.x4.shared.b16 {%0,%1,%2,%3}, [%4];"
        : "=r"(r[0]), "=r"(r[1]), "=r"(r[2]), "=r"(r[3]) : "r"(a));
}
__device__ __forceinline__ void ldsm4t(uint32_t* r, uint32_t a) {
    asm volatile("ldmatrix.sync.aligned.m8n8.x4.trans.shared.b16 {%0,%1,%2,%3}, [%4];"
        : "=r"(r[0]), "=r"(r[1]), "=r"(r[2]), "=r"(r[3]) : "r"(a));
}
__device__ __forceinline__ void mma16816(float* c, const uint32_t* a, const uint32_t* b) {
    asm volatile(
        "mma.sync.aligned.m16n8k16.row.col.f32.bf16.bf16.f32 "
        "{%0,%1,%2,%3}, {%4,%5,%6,%7}, {%8,%9}, {%0,%1,%2,%3};"
        : "+f"(c[0]), "+f"(c[1]), "+f"(c[2]), "+f"(c[3])
        : "r"(a[0]), "r"(a[1]), "r"(a[2]), "r"(a[3]), "r"(b[0]), "r"(b[1]));
}

#define CP_ASYNC(dst, src) \
    asm volatile("cp.async.cg.shared.global [%0], [%1], 16;" :: "r"(dst), "l"(src))
#define CP_COMMIT() asm volatile("cp.async.commit_group;" ::: "memory")
#define CP_WAIT1()  asm volatile("cp.async.wait_group 1;" ::: "memory")
#define CP_WAIT0()  asm volatile("cp.async.wait_group 0;" ::: "memory")

// ---------------------------------------------------------------------------
// split fp32 -> bf16 hi + lo (optionally adding a length-1024 vector per row)
// ---------------------------------------------------------------------------
__global__ void split_bf16(const float4* __restrict__ in,
                           __nv_bfloat162* __restrict__ hi,
                           __nv_bfloat162* __restrict__ lo,
                           const float4* __restrict__ add, int n4)
{
    int i = blockIdx.x * blockDim.x + threadIdx.x;
    if (i >= n4) return;
    float4 x = in[i];
    if (add) {
        float4 a = add[i & 255];
        x.x += a.x; x.y += a.y; x.z += a.z; x.w += a.w;
    }
    __nv_bfloat16 hx = __float2bfloat16(x.x), hy = __float2bfloat16(x.y);
    __nv_bfloat16 hz = __float2bfloat16(x.z), hw = __float2bfloat16(x.w);
    hi[i*2+0] = __halves2bfloat162(hx, hy);
    hi[i*2+1] = __halves2bfloat162(hz, hw);
    __nv_bfloat16 lx = __float2bfloat16(x.x - __bfloat162float(hx));
    __nv_bfloat16 ly = __float2bfloat16(x.y - __bfloat162float(hy));
    __nv_bfloat16 lz = __float2bfloat16(x.z - __bfloat162float(hz));
    __nv_bfloat16 lw = __float2bfloat16(x.w - __bfloat162float(hw));
    lo[i*2+0] = __halves2bfloat162(lx, ly);
    lo[i*2+1] = __halves2bfloat162(lz, lw);
}

// ---------------------------------------------------------------------------
// HMMA GEMM: C[M,1024] = A[M,1024] @ W[1024,1024]^T + bias, bf16-split 3-term.
// 128x128 CTA tile, BK=32, 8 warps (warp tile 64x32), cp.async double-buffer.
// smem tile: 128 rows x 40 bf16 (pad 8) = 10240 B. 4 tiles/buf, 2 bufs = 80 KB.
// ---------------------------------------------------------------------------
#define GLD 40
#define GTB 10240   // tile bytes

__device__ __forceinline__ void gemm_issue(
    uint32_t sb, int buf, int c, int tid,
    const __nv_bfloat16* Ah, const __nv_bfloat16* Al,
    const __nv_bfloat16* Wh, const __nv_bfloat16* Wl, int m0, int n0)
{
    const int k0 = c * 32;
    const uint32_t base = sb + buf * 4 * GTB;
#pragma unroll
    for (int p = 0; p < 2; p++) {
        int ch = tid + p * 256;          // 0..511
        int r = ch >> 2, s = ch & 3;
        uint32_t d = base + (uint32_t)(r * GLD + s * 8) * 2;
        size_t ga = (size_t)(m0 + r) * 1024 + k0 + s * 8;
        size_t gw = (size_t)(n0 + r) * 1024 + k0 + s * 8;
        CP_ASYNC(d,             Ah + ga);
        CP_ASYNC(d + GTB,       Al + ga);
        CP_ASYNC(d + 2*GTB,     Wh + gw);
        CP_ASYNC(d + 3*GTB,     Wl + gw);
    }
}

__global__ void __launch_bounds__(256) hm_gemm(
    const __nv_bfloat16* __restrict__ Ah, const __nv_bfloat16* __restrict__ Al,
    const __nv_bfloat16* __restrict__ Wh, const __nv_bfloat16* __restrict__ Wl,
    const float* __restrict__ bias, float* __restrict__ C, int M)
{
    extern __shared__ __nv_bfloat16 sm[];
    const int tid = threadIdx.x, w = tid >> 5, lane = tid & 31;
    const int n0 = blockIdx.x * 128, m0 = blockIdx.y * 128;
    const int wm = (w & 1) * 64, wn = (w >> 1) * 32;
    const uint32_t sb = smem_u32(sm);
    const int lr = lane & 7, li = lane >> 3;

    float acc[4][4][4];
#pragma unroll
    for (int a = 0; a < 4; a++)
#pragma unroll
        for (int b = 0; b < 4; b++)
#pragma unroll
            for (int k = 0; k < 4; k++) acc[a][b][k] = 0.f;

    gemm_issue(sb, 0, 0, tid, Ah, Al, Wh, Wl, m0, n0);
    CP_COMMIT();

    for (int c = 0; c < 32; c++) {
        if (c < 31) {
            gemm_issue(sb, (c + 1) & 1, c + 1, tid, Ah, Al, Wh, Wl, m0, n0);
            CP_COMMIT();
            CP_WAIT1();
        } else {
            CP_WAIT0();
        }
        __syncthreads();

        const uint32_t bb = sb + (c & 1) * 4 * GTB;
#pragma unroll
        for (int ks = 0; ks < 2; ks++) {
            uint32_t ahf[4][4], alf[4][4];
            const uint32_t acol = (uint32_t)(ks * 16 + (li >> 1) * 8) * 2;
            const uint32_t arow0 = (uint32_t)(wm + (li & 1) * 8 + lr);
#pragma unroll
            for (int mt = 0; mt < 4; mt++) {
                uint32_t ao = bb + (arow0 + mt * 16) * (GLD * 2) + acol;
                ldsm4(ahf[mt], ao);
                ldsm4(alf[mt], ao + GTB);
            }
            uint32_t bhf[2][4], blf[2][4];
            const uint32_t bcol = (uint32_t)(ks * 16 + (li & 1) * 8) * 2;
            const uint32_t brow0 = (uint32_t)(wn + (li >> 1) * 8 + lr);
#pragma unroll
            for (int nb = 0; nb < 2; nb++) {
                uint32_t bo = bb + 2*GTB + (brow0 + nb * 16) * (GLD * 2) + bcol;
                ldsm4(bhf[nb], bo);
                ldsm4(blf[nb], bo + GTB);
            }
#pragma unroll
            for (int mt = 0; mt < 4; mt++)
#pragma unroll
                for (int nt = 0; nt < 4; nt++) {
                    const uint32_t* bh = &bhf[nt >> 1][(nt & 1) * 2];
                    const uint32_t* bl = &blf[nt >> 1][(nt & 1) * 2];
                    mma16816(acc[mt][nt], ahf[mt], bh);
                    mma16816(acc[mt][nt], ahf[mt], bl);
                    mma16816(acc[mt][nt], alf[mt], bh);
                }
        }
        __syncthreads();
    }

#pragma unroll
    for (int mt = 0; mt < 4; mt++) {
        int m = m0 + wm + mt * 16 + (lane >> 2);
        float* r0 = C + (size_t)m * 1024 + n0 + wn;
        float* r8 = r0 + (size_t)8 * 1024;
        const float* bp = bias + n0 + wn;
#pragma unroll
        for (int nt = 0; nt < 4; nt++) {
            int col = nt * 8 + (lane & 3) * 2;
            float2 bb2 = *(const float2*)(bp + col);
            float2 o0 = { acc[mt][nt][0] + bb2.x, acc[mt][nt][1] + bb2.y };
            float2 o8 = { acc[mt][nt][2] + bb2.x, acc[mt][nt][3] + bb2.y };
            *(float2*)(r0 + col) = o0;
            *(float2*)(r8 + col) = o8;
        }
    }
}

// ---------------------------------------------------------------------------
// HMMA batched scores, z = b*16+n.  K=64 single shot. LD=72 pad.
//   mode0 (AC): C[i,j] = (q+u)[i,b,n,:]·k[j,b,n,:]
//   mode1 (BD): C[i,l] = (q+v)[i,b,n,:]·kr[l,n,:]
// smem: 4 tiles x 128x72x2 = 73728 B
// ---------------------------------------------------------------------------
#define SLD 72
#define STB 18432

__global__ void __launch_bounds__(256) hm_scores(
    const __nv_bfloat16* __restrict__ Ah, const __nv_bfloat16* __restrict__ Al,
    const __nv_bfloat16* __restrict__ Bh, const __nv_bfloat16* __restrict__ Bl,
    float* __restrict__ Out, int mode)
{
    extern __shared__ __nv_bfloat16 sm[];
    const int tid = threadIdx.x, w = tid >> 5, lane = tid & 31;
    const int z = blockIdx.z, b = z >> 4, n = z & 15;
    const int j0 = blockIdx.x * 128, i0 = blockIdx.y * 128;
    const int wm = (w & 1) * 64, wn = (w >> 1) * 32;
    const uint32_t sb = smem_u32(sm);
    const int lr = lane & 7, li = lane >> 3;

    // load 4 tiles: A hi/lo (rows (i0+r)*4+b), B hi/lo
#pragma unroll
    for (int p = 0; p < 4; p++) {
        int ch = tid + p * 256;          // 0..1023
        int r = ch >> 3, s = ch & 7;
        uint32_t d = sb + (uint32_t)(r * SLD + s * 8) * 2;
        size_t ga = ((size_t)(i0 + r) * 4 + b) * 1024 + n * 64 + s * 8;
        size_t gb = mode ? ((size_t)(j0 + r) * 1024 + n * 64 + s * 8)
                         : (((size_t)(j0 + r) * 4 + b) * 1024 + n * 64 + s * 8);
        CP_ASYNC(d,           Ah + ga);
        CP_ASYNC(d + STB,     Al + ga);
        CP_ASYNC(d + 2*STB,   Bh + gb);
        CP_ASYNC(d + 3*STB,   Bl + gb);
    }
    CP_COMMIT();
    CP_WAIT0();
    __syncthreads();

    float acc[4][4][4];
#pragma unroll
    for (int a = 0; a < 4; a++)
#pragma unroll
        for (int c = 0; c < 4; c++)
#pragma unroll
            for (int k = 0; k < 4; k++) acc[a][c][k] = 0.f;

#pragma unroll
    for (int ks = 0; ks < 4; ks++) {
        uint32_t ahf[4][4], alf[4][4];
        const uint32_t acol = (uint32_t)(ks * 16 + (li >> 1) * 8) * 2;
        const uint32_t arow0 = (uint32_t)(wm + (li & 1) * 8 + lr);
#pragma unroll
        for (int mt = 0; mt < 4; mt++) {
            uint32_t ao = sb + (arow0 + mt * 16) * (SLD * 2) + acol;
            ldsm4(ahf[mt], ao);
            ldsm4(alf[mt], ao + STB);
        }
        uint32_t bhf[2][4], blf[2][4];
        const uint32_t bcol = (uint32_t)(ks * 16 + (li & 1) * 8) * 2;
        const uint32_t brow0 = (uint32_t)(wn + (li >> 1) * 8 + lr);
#pragma unroll
        for (int nb = 0; nb < 2; nb++) {
            uint32_t bo = sb + 2*STB + (brow0 + nb * 16) * (SLD * 2) + bcol;
            ldsm4(bhf[nb], bo);
            ldsm4(blf[nb], bo + STB);
        }
#pragma unroll
        for (int mt = 0; mt < 4; mt++)
#pragma unroll
            for (int nt = 0; nt < 4; nt++) {
                const uint32_t* bh = &bhf[nt >> 1][(nt & 1) * 2];
                const uint32_t* bl = &blf[nt >> 1][(nt & 1) * 2];
                mma16816(acc[mt][nt], ahf[mt], bh);
                mma16816(acc[mt][nt], ahf[mt], bl);
                mma16816(acc[mt][nt], alf[mt], bh);
            }
    }

    const size_t obase = (size_t)z * PLANE;
#pragma unroll
    for (int mt = 0; mt < 4; mt++) {
        int row = i0 + wm + mt * 16 + (lane >> 2);
        float* r0 = Out + obase + (size_t)row * 2048 + j0 + wn;
        float* r8 = r0 + (size_t)8 * 2048;
#pragma unroll
        for (int nt = 0; nt < 4; nt++) {
            int col = nt * 8 + (lane & 3) * 2;
            float2 o0 = { acc[mt][nt][0], acc[mt][nt][1] };
            float2 o8 = { acc[mt][nt][2], acc[mt][nt][3] };
            *(float2*)(r0 + col) = o0;
            *(float2*)(r8 + col) = o8;
        }
    }
}

// ---------------------------------------------------------------------------
// HMMA attn@V: O1[(i*4+b)*1024 + n*64+d] = sum_j ATT[z,i,j] * V[(j*4+b), n*64+d]
// CTA tile M=128(i) N=64(d), K=2048(j) in 32 chunks of 64. 8 warps: 32x32 each.
// A (ATT) row-major via ldsm4; B (V, row-major j x d) via ldsm4t (trans).
// smem/buf: ATTh/l 128x72x2 = 18432 ea; Vh/l 64x72x2 = 9216 ea => 55296 B; x2 bufs
// ---------------------------------------------------------------------------
#define VTB 9216
#define ABUF 55296

__device__ __forceinline__ void attnv_issue(
    uint32_t sb, int buf, int c, int tid, int i0, int b, int n, size_t zbase)
{
    const uint32_t base = sb + buf * ABUF;
#pragma unroll
    for (int p = 0; p < 4; p++) {
        int ch = tid + p * 256;          // 0..1023
        int r = ch >> 3, s = ch & 7;
        uint32_t d = base + (uint32_t)(r * SLD + s * 8) * 2;
        size_t g = zbase + (size_t)(i0 + r) * 2048 + c * 64 + s * 8;
        CP_ASYNC(d,       g_ATTh + g);
        CP_ASYNC(d + STB, g_ATTl + g);
    }
#pragma unroll
    for (int p = 0; p < 2; p++) {
        int ch = tid + p * 256;          // 0..511
        int r = ch >> 3, s = ch & 7;
        uint32_t d = base + 2*STB + (uint32_t)(r * SLD + s * 8) * 2;
        size_t g = ((size_t)(c * 64 + r) * 4 + b) * 1024 + n * 64 + s * 8;
        CP_ASYNC(d,       g_Vh + g);
        CP_ASYNC(d + VTB, g_Vl + g);
    }
}

__global__ void __launch_bounds__(256) hm_attnv()
{
    extern __shared__ __nv_bfloat16 sm[];
    const int tid = threadIdx.x, w = tid >> 5, lane = tid & 31;
    const int z = blockIdx.y, b = z >> 4, n = z & 15;
    const int i0 = blockIdx.x * 128;
    const int wm = (w & 3) * 32, wn = (w >> 2) * 32;
    const size_t zbase = (size_t)z * PLANE;
    const uint32_t sb = smem_u32(sm);
    const int lr = lane & 7, li = lane >> 3;

    float acc[2][4][4];
#pragma unroll
    for (int a = 0; a < 2; a++)
#pragma unroll
        for (int c = 0; c < 4; c++)
#pragma unroll
            for (int k = 0; k < 4; k++) acc[a][c][k] = 0.f;

    attnv_issue(sb, 0, 0, tid, i0, b, n, zbase);
    CP_COMMIT();

    for (int c = 0; c < 32; c++) {
        if (c < 31) {
            attnv_issue(sb, (c + 1) & 1, c + 1, tid, i0, b, n, zbase);
            CP_COMMIT();
            CP_WAIT1();
        } else {
            CP_WAIT0();
        }
        __syncthreads();

        const uint32_t bb = sb + (c & 1) * ABUF;
#pragma unroll
        for (int ks = 0; ks < 4; ks++) {
            uint32_t ahf[2][4], alf[2][4];
            const uint32_t acol = (uint32_t)(ks * 16 + (li >> 1) * 8) * 2;
            const uint32_t arow0 = (uint32_t)(wm + (li & 1) * 8 + lr);
#pragma unroll
            for (int mt = 0; mt < 2; mt++) {
                uint32_t ao = bb + (arow0 + mt * 16) * (SLD * 2) + acol;
                ldsm4(ahf[mt], ao);
                ldsm4(alf[mt], ao + STB);
            }
            // V: rows = j (k dim), cols = d (n dim). trans ldmatrix.
            uint32_t bhf[2][4], blf[2][4];
            const uint32_t vrow0 = (uint32_t)(ks * 16 + (li & 1) * 8 + lr);
#pragma unroll
            for (int nb = 0; nb < 2; nb++) {
                uint32_t vcol = (uint32_t)(wn + nb * 16 + (li >> 1) * 8) * 2;
                uint32_t bo = bb + 2*STB + vrow0 * (SLD * 2) + vcol;
                ldsm4t(bhf[nb], bo);
                ldsm4t(blf[nb], bo + VTB);
            }
#pragma unroll
            for (int mt = 0; mt < 2; mt++)
#pragma unroll
                for (int nt = 0; nt < 4; nt++) {
                    const uint32_t* bh = &bhf[nt >> 1][(nt & 1) * 2];
                    const uint32_t* bl = &blf[nt >> 1][(nt & 1) * 2];
                    mma16816(acc[mt][nt], ahf[mt], bh);
                    mma16816(acc[mt][nt], ahf[mt], bl);
                    mma16816(acc[mt][nt], alf[mt], bh);
                }
        }
        __syncthreads();
    }

#pragma unroll
    for (int mt = 0; mt < 2; mt++) {
        int i = i0 + wm + mt * 16 + (lane >> 2);
        float* o0 = g_O1 + ((size_t)i * 4 + b) * 1024 + n * 64 + wn;
        float* o8 = g_O1 + ((size_t)(i + 8) * 4 + b) * 1024 + n * 64 + wn;
#pragma unroll
        for (int nt = 0; nt < 4; nt++) {
            int col = nt * 8 + (lane & 3) * 2;
            float2 v0 = { acc[mt][nt][0], acc[mt][nt][1] };
            float2 v8 = { acc[mt][nt][2], acc[mt][nt][3] };
            *(float2*)(o0 + col) = v0;
            *(float2*)(o8 + col) = v8;
        }
    }
}

// ---------------------------------------------------------------------------
// Gather kv_in, natural flat order: row r = b*2048 + j
// ---------------------------------------------------------------------------
__global__ void gather_kv(const float4* __restrict__ te, const float4* __restrict__ mems)
{
    int idx = blockIdx.x * blockDim.x + threadIdx.x;
    int row = idx >> 8, c = idx & 255;
    int b = row >> 11, j = row & 2047;
    float4 v;
    if (j < 1024) v = te  [((size_t)b * 1024 + j) * 256 + c];
    else          v = mems[((size_t)b * 2048 + (j - 1024)) * 256 + c];
    ((float4*)g_KV)[idx] = v;
}

// ---------------------------------------------------------------------------
// Softmax over heads: rel-shift BD, faithful mask remap, write ATT as bf16 hi/lo
// ---------------------------------------------------------------------------
__global__ void softmax_heads(const float* __restrict__ amask)
{
    const int j = blockIdx.x * 256 + threadIdx.x;
    const int i = blockIdx.y;
    const int b = blockIdx.z;
    const int l = j + 1023 - i;
    const bool lv = (l < 2048);
    const int bprime = i >> 8;

    const size_t base = ((size_t)b * 16 * 1024 + i) * 2048;
    float s[16];
    float mx = -1e30f;
#pragma unroll
    for (int n = 0; n < 16; n++) {
        float ac = g_AC[base + (size_t)n * PLANE + j];
        float bd = lv ? g_BD[base + (size_t)n * PLANE + l] : 0.f;
        float val = (ac + bd) * 0.125f;
        int jp = (j * 64 + b * 16 + n) & 2047;
        float m = (jp < 1024) ? 1.f : amask[(size_t)bprime * 1024 + (jp - 1024)];
        val -= (1.f - m) * 1e9f;
        s[n] = val;
        mx = fmaxf(mx, val);
    }
    float sum = 0.f;
#pragma unroll
    for (int n = 0; n < 16; n++) { s[n] = __expf(s[n] - mx); sum += s[n]; }
    float inv = 1.f / sum;
#pragma unroll
    for (int n = 0; n < 16; n++) {
        float a = s[n] * inv;
        __nv_bfloat16 ah = __float2bfloat16(a);
        __nv_bfloat16 al = __float2bfloat16(a - __bfloat162float(ah));
        g_ATTh[base + (size_t)n * PLANE + j] = ah;
        g_ATTl[base + (size_t)n * PLANE + j] = al;
    }
}

// ---------------------------------------------------------------------------
__global__ void write_mems(const float4* __restrict__ mems,
                           const float4* __restrict__ out,
                           float4* __restrict__ dst)
{
    int idx = blockIdx.x * blockDim.x + threadIdx.x;
    int row = idx >> 8, c = idx & 255;
    int b = row >> 11, pos = row & 2047;
    float4 v;
    if (pos < 1024) v = mems[idx];
    else            v = out[(((size_t)b * 1024) + (pos - 1024)) * 256 + c];
    dst[idx] = v;
}

// ---------------------------------------------------------------------------
extern "C" void kernel_launch(void* const* d_in, const int* in_sizes, int n_in,
                              void* d_out, int out_size)
{
    const float* TE    = (const float*)d_in[0];
    const float* REL   = (const float*)d_in[1];
    const float* MEMS  = (const float*)d_in[2];
    const float* AMASK = (const float*)d_in[3];
    const float* Wq = (const float*)d_in[4],  *bq = (const float*)d_in[5];
    const float* Wk = (const float*)d_in[6],  *bk = (const float*)d_in[7];
    const float* Wv = (const float*)d_in[8],  *bv = (const float*)d_in[9];
    const float* Wr = (const float*)d_in[10], *br = (const float*)d_in[11];
    const float* Wo = (const float*)d_in[12], *bo = (const float*)d_in[13];
    const float* u  = (const float*)d_in[14];
    const float* v  = (const float*)d_in[15];
    float* out = (float*)d_out;

    const int G_SMEM = 2 * 4 * GTB;   // 81920
    const int S_SMEM = 4 * STB;       // 73728
    const int A_SMEM = 2 * ABUF;      // 110592
    cudaFuncSetAttribute(hm_gemm,   cudaFuncAttributeMaxDynamicSharedMemorySize, G_SMEM);
    cudaFuncSetAttribute(hm_scores, cudaFuncAttributeMaxDynamicSharedMemorySize, S_SMEM);
    cudaFuncSetAttribute(hm_attnv,  cudaFuncAttributeMaxDynamicSharedMemorySize, A_SMEM);

    float *pKV, *pQ, *pK, *pV, *pR, *pO1, *pAC, *pBD;
    cudaGetSymbolAddress((void**)&pKV, g_KV);
    cudaGetSymbolAddress((void**)&pQ,  g_Q);
    cudaGetSymbolAddress((void**)&pK,  g_K);
    cudaGetSymbolAddress((void**)&pV,  g_V);
    cudaGetSymbolAddress((void**)&pR,  g_R);
    cudaGetSymbolAddress((void**)&pO1, g_O1);
    cudaGetSymbolAddress((void**)&pAC, g_AC);
    cudaGetSymbolAddress((void**)&pBD, g_BD);

    __nv_bfloat16 *pTEh, *pTEl, *pKVh, *pKVl, *pRELh, *pRELl, *pO1h, *pO1l;
    __nv_bfloat16 *pWh, *pWl, *pQUh, *pQUl, *pQVh, *pQVl, *pKh, *pKl, *pRh, *pRl, *pVh, *pVl;
    cudaGetSymbolAddress((void**)&pTEh,  g_TEh);  cudaGetSymbolAddress((void**)&pTEl,  g_TEl);
    cudaGetSymbolAddress((void**)&pKVh,  g_KVh);  cudaGetSymbolAddress((void**)&pKVl,  g_KVl);
    cudaGetSymbolAddress((void**)&pRELh, g_RELh); cudaGetSymbolAddress((void**)&pRELl, g_RELl);
    cudaGetSymbolAddress((void**)&pO1h,  g_O1h);  cudaGetSymbolAddress((void**)&pO1l,  g_O1l);
    cudaGetSymbolAddress((void**)&pWh,   g_Wh);   cudaGetSymbolAddress((void**)&pWl,   g_Wl);
    cudaGetSymbolAddress((void**)&pQUh,  g_QUh);  cudaGetSymbolAddress((void**)&pQUl,  g_QUl);
    cudaGetSymbolAddress((void**)&pQVh,  g_QVh);  cudaGetSymbolAddress((void**)&pQVl,  g_QVl);
    cudaGetSymbolAddress((void**)&pKh,   g_Kh);   cudaGetSymbolAddress((void**)&pKl,   g_Kl);
    cudaGetSymbolAddress((void**)&pRh,   g_Rh);   cudaGetSymbolAddress((void**)&pRl,   g_Rl);
    cudaGetSymbolAddress((void**)&pVh,   g_Vh);   cudaGetSymbolAddress((void**)&pVl,   g_Vl);

    const size_t WSZ = (size_t)1024 * 1024;

    // 1. gather kv rows
    gather_kv<<<8192, 256>>>((const float4*)TE, (const float4*)MEMS);

    // 2. bf16 hi/lo splits of GEMM inputs + weights
    split_bf16<<<4096, 256>>>((const float4*)TE,  (__nv_bfloat162*)pTEh,  (__nv_bfloat162*)pTEl,  nullptr, 1048576);
    split_bf16<<<8192, 256>>>((const float4*)pKV, (__nv_bfloat162*)pKVh,  (__nv_bfloat162*)pKVl,  nullptr, 2097152);
    split_bf16<<<2048, 256>>>((const float4*)REL, (__nv_bfloat162*)pRELh, (__nv_bfloat162*)pRELl, nullptr, 524288);
    split_bf16<<<1024, 256>>>((const float4*)Wq, (__nv_bfloat162*)(pWh + 0*WSZ), (__nv_bfloat162*)(pWl + 0*WSZ), nullptr, 262144);
    split_bf16<<<1024, 256>>>((const float4*)Wk, (__nv_bfloat162*)(pWh + 1*WSZ), (__nv_bfloat162*)(pWl + 1*WSZ), nullptr, 262144);
    split_bf16<<<1024, 256>>>((const float4*)Wv, (__nv_bfloat162*)(pWh + 2*WSZ), (__nv_bfloat162*)(pWl + 2*WSZ), nullptr, 262144);
    split_bf16<<<1024, 256>>>((const float4*)Wr, (__nv_bfloat162*)(pWh + 3*WSZ), (__nv_bfloat162*)(pWl + 3*WSZ), nullptr, 262144);
    split_bf16<<<1024, 256>>>((const float4*)Wo, (__nv_bfloat162*)(pWh + 4*WSZ), (__nv_bfloat162*)(pWl + 4*WSZ), nullptr, 262144);

    // 3. projections on HMMA tensor path
    hm_gemm<<<dim3(8, 32), 256, G_SMEM>>>(pTEh,  pTEl,  pWh + 0*WSZ, pWl + 0*WSZ, bq, pQ, 4096);
    hm_gemm<<<dim3(8, 64), 256, G_SMEM>>>(pKVh,  pKVl,  pWh + 1*WSZ, pWl + 1*WSZ, bk, pK, 8192);
    hm_gemm<<<dim3(8, 64), 256, G_SMEM>>>(pKVh,  pKVl,  pWh + 2*WSZ, pWl + 2*WSZ, bv, pV, 8192);
    hm_gemm<<<dim3(8, 16), 256, G_SMEM>>>(pRELh, pRELl, pWh + 3*WSZ, pWl + 3*WSZ, br, pR, 2048);

    // 4. splits for scores / attnv
    split_bf16<<<4096, 256>>>((const float4*)pQ, (__nv_bfloat162*)pQUh, (__nv_bfloat162*)pQUl, (const float4*)u, 1048576);
    split_bf16<<<4096, 256>>>((const float4*)pQ, (__nv_bfloat162*)pQVh, (__nv_bfloat162*)pQVl, (const float4*)v, 1048576);
    split_bf16<<<8192, 256>>>((const float4*)pK, (__nv_bfloat162*)pKh,  (__nv_bfloat162*)pKl,  nullptr, 2097152);
    split_bf16<<<2048, 256>>>((const float4*)pR, (__nv_bfloat162*)pRh,  (__nv_bfloat162*)pRl,  nullptr, 524288);
    split_bf16<<<8192, 256>>>((const float4*)pV, (__nv_bfloat162*)pVh,  (__nv_bfloat162*)pVl,  nullptr, 2097152);

    // 5. score GEMMs
    hm_scores<<<dim3(16, 8, 64), 256, S_SMEM>>>(pQUh, pQUl, pKh, pKl, pAC, 0);
    hm_scores<<<dim3(16, 8, 64), 256, S_SMEM>>>(pQVh, pQVl, pRh, pRl, pBD, 1);

    // 6. rel-shift + mask + softmax over heads (writes bf16 hi/lo ATT)
    softmax_heads<<<dim3(8, 1024, 4), 256>>>(AMASK);

    // 7. attn @ V on HMMA
    hm_attnv<<<dim3(8, 64), 256, A_SMEM>>>();

    // 8. O projection -> d_out
    split_bf16<<<4096, 256>>>((const float4*)pO1, (__nv_bfloat162*)pO1h, (__nv_bfloat162*)pO1l, nullptr, 1048576);
    hm_gemm<<<dim3(8, 32), 256, G_SMEM>>>(pO1h, pO1l, pWh + 4*WSZ, pWl + 4*WSZ, bo, out, 4096);

    // 9. mems_new
    if (out_size >= 12582912)
        write_mems<<<8192, 256>>>((const float4*)MEMS, (const float4*)out,
                                  (float4*)(out + 4194304));
}